// round 3
// baseline (speedup 1.0000x reference)
#include <cuda_runtime.h>
#include <cuda_bf16.h>
#include <math.h>
#include <stdint.h>

// Problem constants
#define Bn   32
#define DQ   512
#define DK   512
#define NK   16
#define Hn   8
#define Tt   12
#define Nn   207
#define Cc   64
#define TNC  (Tt*Nn*Cc)      // 158976
#define Mrows (Bn*NK)        // 512
#define Ncols (Hn*DQ)        // 4096

// Device scratch
__device__ float g_Xt[Mrows * DK];   // keys transposed
__device__ float g_att[Mrows];       // logits accum

// ---------------------------------------------------------------------------
// Kernel 0: transpose keys [B, DK, NK] -> Xt [B*NK, DK]; zero att accum.
// ---------------------------------------------------------------------------
__global__ void prep_kernel(const float* __restrict__ keys, float* __restrict__ Xt,
                            float* __restrict__ att) {
    __shared__ float s[32][17];
    int b = blockIdx.x;
    int tid = threadIdx.x;             // 512
    if (b == 0 && tid < Mrows) att[tid] = 0.0f;

    int d_ld = tid >> 4, k_ld = tid & 15;
    int k_st = tid >> 5, d_st = tid & 31;
    const float* kb = keys + (size_t)b * DK * NK;
    float* xb = Xt + (size_t)b * NK * DK;

    for (int d0 = 0; d0 < DK; d0 += 32) {
        s[d_ld][k_ld] = kb[(d0 + d_ld) * NK + k_ld];
        __syncthreads();
        xb[k_st * DK + d0 + d_st] = s[d_st][k_st];
        __syncthreads();
    }
}

// ---------------------------------------------------------------------------
// tf32 helpers
// ---------------------------------------------------------------------------
__device__ __forceinline__ float to_tf32(float x) {
    uint32_t u;
    asm("cvt.rna.tf32.f32 %0, %1;" : "=r"(u) : "f"(x));
    return __uint_as_float(u);
}

__device__ __forceinline__ void mma_tf32(float* c, const uint32_t* a,
                                         uint32_t b0, uint32_t b1) {
    asm volatile(
        "mma.sync.aligned.m16n8k8.row.col.f32.tf32.tf32.f32 "
        "{%0,%1,%2,%3}, {%4,%5,%6,%7}, {%8,%9}, {%0,%1,%2,%3};"
        : "+f"(c[0]), "+f"(c[1]), "+f"(c[2]), "+f"(c[3])
        : "r"(a[0]), "r"(a[1]), "r"(a[2]), "r"(a[3]), "r"(b0), "r"(b1));
}

// ---------------------------------------------------------------------------
// Kernel A: tf32 tensor GEMM, double-buffered smem, fused ReLU/bias/Q-dot.
// BM=128, BN=128, BK=32, 256 threads (2x4 warps), warp tile 64x32.
// Dynamic smem: As[2][128*36] Bs[2][128*36] Qs[8*128] bias[128] part[128]
// ---------------------------------------------------------------------------
#define SSTR 36
#define TILE_F (128 * SSTR)
#define GEMM_SMEM_BYTES ((2*TILE_F*2 + 8*128 + 128 + 128) * 4)

__global__ __launch_bounds__(256, 1)
void gemm_att_tc(const float* __restrict__ Xt, const float* __restrict__ W,
                 const float* __restrict__ bias, const float* __restrict__ query,
                 float* __restrict__ att) {
    extern __shared__ float smem[];
    float* As    = smem;                  // 2 * TILE_F
    float* Bs    = As + 2 * TILE_F;       // 2 * TILE_F
    float* Qs    = Bs + 2 * TILE_F;       // 8*128
    float* biasS = Qs + 8 * 128;          // 128
    float* partS = biasS + 128;           // 128

    int tid  = threadIdx.x;
    int lane = tid & 31;
    int warp = tid >> 5;
    int warp_m = warp >> 2;        // 0..1
    int warp_n = warp & 3;         // 0..3
    int g   = lane >> 2;           // 0..7
    int tig = lane & 3;            // 0..3

    int c0 = blockIdx.x * 128;
    int m0 = blockIdx.y * 128;
    int q0 = c0 & (DQ - 1);
    int b0 = m0 >> 4;

    for (int i = tid; i < 8 * 128; i += 256)
        Qs[i] = query[(b0 + (i >> 7)) * DQ + q0 + (i & 127)];
    if (tid < 128) { biasS[tid] = bias[c0 + tid]; partS[tid] = 0.0f; }

    float acc[4][4][4] = {};

    int lr = tid >> 3;             // 0..31
    int lc = (tid & 7) << 2;       // 0..28 step 4

    float4 av[4], bv[4];
    // prologue: load tile kt=0
    #pragma unroll
    for (int rr = 0; rr < 4; rr++) {
        int r = lr + rr * 32;
        av[rr] = *(const float4*)&Xt[(size_t)(m0 + r) * DK + lc];
        bv[rr] = *(const float4*)&W [(size_t)(c0 + r) * DK + lc];
    }
    #pragma unroll
    for (int rr = 0; rr < 4; rr++) {
        int r = lr + rr * 32;
        float* pa = &As[r * SSTR + lc];
        pa[0] = to_tf32(av[rr].x); pa[1] = to_tf32(av[rr].y);
        pa[2] = to_tf32(av[rr].z); pa[3] = to_tf32(av[rr].w);
        float* pb = &Bs[r * SSTR + lc];
        pb[0] = to_tf32(bv[rr].x); pb[1] = to_tf32(bv[rr].y);
        pb[2] = to_tf32(bv[rr].z); pb[3] = to_tf32(bv[rr].w);
    }
    __syncthreads();

    for (int it = 0; it < 16; it++) {
        int buf = it & 1;
        const float* Ab = As + buf * TILE_F;
        const float* Bb = Bs + buf * TILE_F;

        // prefetch next tile into registers (overlaps MMA below)
        if (it < 15) {
            int kt = (it + 1) * 32;
            #pragma unroll
            for (int rr = 0; rr < 4; rr++) {
                int r = lr + rr * 32;
                av[rr] = *(const float4*)&Xt[(size_t)(m0 + r) * DK + kt + lc];
                bv[rr] = *(const float4*)&W [(size_t)(c0 + r) * DK + kt + lc];
            }
        }

        // MMA over current buffer
        #pragma unroll
        for (int ks = 0; ks < 4; ks++) {
            int k = ks * 8 + tig;
            uint32_t a[4][4];
            #pragma unroll
            for (int mt = 0; mt < 4; mt++) {
                int mbase = warp_m * 64 + mt * 16 + g;
                a[mt][0] = __float_as_uint(Ab[(mbase    ) * SSTR + k    ]);
                a[mt][1] = __float_as_uint(Ab[(mbase + 8) * SSTR + k    ]);
                a[mt][2] = __float_as_uint(Ab[(mbase    ) * SSTR + k + 4]);
                a[mt][3] = __float_as_uint(Ab[(mbase + 8) * SSTR + k + 4]);
            }
            #pragma unroll
            for (int nt = 0; nt < 4; nt++) {
                int nbase = warp_n * 32 + nt * 8 + g;
                uint32_t b0r = __float_as_uint(Bb[nbase * SSTR + k    ]);
                uint32_t b1r = __float_as_uint(Bb[nbase * SSTR + k + 4]);
                #pragma unroll
                for (int mt = 0; mt < 4; mt++)
                    mma_tf32(acc[mt][nt], a[mt], b0r, b1r);
            }
        }

        // store prefetched tile to alternate buffer (old contents already consumed)
        if (it < 15) {
            float* Aa = As + (buf ^ 1) * TILE_F;
            float* Ba = Bs + (buf ^ 1) * TILE_F;
            #pragma unroll
            for (int rr = 0; rr < 4; rr++) {
                int r = lr + rr * 32;
                float* pa = &Aa[r * SSTR + lc];
                pa[0] = to_tf32(av[rr].x); pa[1] = to_tf32(av[rr].y);
                pa[2] = to_tf32(av[rr].z); pa[3] = to_tf32(av[rr].w);
                float* pb = &Ba[r * SSTR + lc];
                pb[0] = to_tf32(bv[rr].x); pb[1] = to_tf32(bv[rr].y);
                pb[2] = to_tf32(bv[rr].z); pb[3] = to_tf32(bv[rr].w);
            }
        }
        __syncthreads();
    }

    // Epilogue: bias + relu + Q-weight, reduce per row
    #pragma unroll
    for (int mt = 0; mt < 4; mt++) {
        int mlo = warp_m * 64 + mt * 16 + g;
        int mhi = mlo + 8;
        const float* q_lo = &Qs[(mlo >> 4) * 128];
        const float* q_hi = &Qs[(mhi >> 4) * 128];
        float p_lo = 0.0f, p_hi = 0.0f;
        #pragma unroll
        for (int nt = 0; nt < 4; nt++) {
            int cl = warp_n * 32 + nt * 8 + 2 * tig;
            float bi0 = biasS[cl], bi1 = biasS[cl + 1];
            p_lo = fmaf(fmaxf(acc[mt][nt][0] + bi0, 0.0f), q_lo[cl],     p_lo);
            p_lo = fmaf(fmaxf(acc[mt][nt][1] + bi1, 0.0f), q_lo[cl + 1], p_lo);
            p_hi = fmaf(fmaxf(acc[mt][nt][2] + bi0, 0.0f), q_hi[cl],     p_hi);
            p_hi = fmaf(fmaxf(acc[mt][nt][3] + bi1, 0.0f), q_hi[cl + 1], p_hi);
        }
        p_lo += __shfl_xor_sync(0xffffffffu, p_lo, 1);
        p_lo += __shfl_xor_sync(0xffffffffu, p_lo, 2);
        p_hi += __shfl_xor_sync(0xffffffffu, p_hi, 1);
        p_hi += __shfl_xor_sync(0xffffffffu, p_hi, 2);
        if (tig == 0) {
            atomicAdd(&partS[mlo], p_lo);
            atomicAdd(&partS[mhi], p_hi);
        }
    }
    __syncthreads();
    if (tid < 128) atomicAdd(&att[m0 + tid], partS[tid]);
}

// ---------------------------------------------------------------------------
// Kernel C: fused softmax + att-weighted V reduction.
// Each block: warp 0 computes the 16-wide softmax for its batch (redundant
// but free on a DRAM-bound kernel). 2 outputs per thread -> 8 LDG.128 MLP.
// ---------------------------------------------------------------------------
__global__ __launch_bounds__(256)
void weighted_v_kernel(const float* __restrict__ V, const float* __restrict__ att,
                       float* __restrict__ out) {
    __shared__ float aw[NK];
    int b = blockIdx.y;
    if (threadIdx.x < 32) {
        int lane = threadIdx.x;
        const float scale = 1.0f / (8.0f * 22.62741699796952f);  // 1/(H*sqrt(512))
        float v = (lane < NK) ? att[b * NK + lane] * scale : -1e30f;
        float m = v;
        #pragma unroll
        for (int o = 8; o; o >>= 1) m = fmaxf(m, __shfl_xor_sync(0xffffffffu, m, o));
        float e = (lane < NK) ? __expf(v - m) : 0.0f;
        float s = e;
        #pragma unroll
        for (int o = 8; o; o >>= 1) s += __shfl_xor_sync(0xffffffffu, s, o);
        if (lane < NK) aw[lane] = e / s;
    }
    __syncthreads();

    float w0 = aw[0],  w1 = aw[1],  w2 = aw[2],  w3 = aw[3];
    float w4 = aw[4],  w5 = aw[5],  w6 = aw[6],  w7 = aw[7];
    float w8 = aw[8],  w9 = aw[9],  wa = aw[10], wb = aw[11];
    float wc = aw[12], wd = aw[13], we = aw[14], wf = aw[15];

    int i0 = (blockIdx.x * 256 + threadIdx.x) * 2;
    if (i0 >= TNC) return;
    const float4* v4 = (const float4*)(V + ((size_t)b * TNC + i0) * NK);
    float4 p0 = __ldcs(v4 + 0), p1 = __ldcs(v4 + 1);
    float4 p2 = __ldcs(v4 + 2), p3 = __ldcs(v4 + 3);
    float4 q0 = __ldcs(v4 + 4), q1 = __ldcs(v4 + 5);
    float4 q2 = __ldcs(v4 + 6), q3 = __ldcs(v4 + 7);

    float s0;
    s0  = p0.x * w0 + p0.y * w1 + p0.z * w2 + p0.w * w3;
    s0 += p1.x * w4 + p1.y * w5 + p1.z * w6 + p1.w * w7;
    s0 += p2.x * w8 + p2.y * w9 + p2.z * wa + p2.w * wb;
    s0 += p3.x * wc + p3.y * wd + p3.z * we + p3.w * wf;
    float s1;
    s1  = q0.x * w0 + q0.y * w1 + q0.z * w2 + q0.w * w3;
    s1 += q1.x * w4 + q1.y * w5 + q1.z * w6 + q1.w * w7;
    s1 += q2.x * w8 + q2.y * w9 + q2.z * wa + q2.w * wb;
    s1 += q3.x * wc + q3.y * wd + q3.z * we + q3.w * wf;

    float2 r = make_float2(s0, s1);
    __stcs((float2*)(out + (size_t)b * TNC + i0), r);
}

// ---------------------------------------------------------------------------
extern "C" void kernel_launch(void* const* d_in, const int* in_sizes, int n_in,
                              void* d_out, int out_size) {
    const float *query = nullptr, *keys = nullptr, *V = nullptr,
                *W = nullptr, *bias = nullptr;
    for (int i = 0; i < n_in; i++) {
        switch (in_sizes[i]) {
            case Bn * DQ:            query = (const float*)d_in[i]; break;
            case Bn * DK * NK:       keys  = (const float*)d_in[i]; break;
            case Bn * TNC * NK:      V     = (const float*)d_in[i]; break;
            case Hn * DQ * DK:       W     = (const float*)d_in[i]; break;
            case Hn * DQ:            bias  = (const float*)d_in[i]; break;
            default: break;
        }
    }
    float* out = (float*)d_out;

    float* Xt;  cudaGetSymbolAddress((void**)&Xt,  g_Xt);
    float* att; cudaGetSymbolAddress((void**)&att, g_att);

    static bool attr_set = false;
    if (!attr_set) {
        cudaFuncSetAttribute(gemm_att_tc,
                             cudaFuncAttributeMaxDynamicSharedMemorySize,
                             GEMM_SMEM_BYTES);
        attr_set = true;
    }

    prep_kernel<<<Bn, 512>>>(keys, Xt, att);

    dim3 gridA(Ncols / 128, Mrows / 128);   // (32, 4)
    gemm_att_tc<<<gridA, 256, GEMM_SMEM_BYTES>>>(Xt, W, bias, query, att);

    dim3 gridC((TNC / 2 + 255) / 256, Bn);  // (311, 32)
    weighted_v_kernel<<<gridC, 256>>>(V, att, out);
}

// round 4
// speedup vs baseline: 1.2140x; 1.2140x over previous
#include <cuda_runtime.h>
#include <cuda_bf16.h>
#include <math.h>
#include <stdint.h>

// Problem constants
#define Bn   32
#define DQ   512
#define DK   512
#define NK   16
#define Hn   8
#define Tt   12
#define Nn   207
#define Cc   64
#define TNC  (Tt*Nn*Cc)      // 158976
#define Mrows (Bn*NK)        // 512
#define Ncols (Hn*DQ)        // 4096

__device__ float g_att[Mrows];       // logits accum -> (softmax in V kernel)

// ---------------------------------------------------------------------------
// mma helper (raw fp32 operands; HW truncates to tf32)
// ---------------------------------------------------------------------------
__device__ __forceinline__ void mma_tf32(float* c, const uint32_t* a,
                                         uint32_t b0, uint32_t b1) {
    asm volatile(
        "mma.sync.aligned.m16n8k8.row.col.f32.tf32.tf32.f32 "
        "{%0,%1,%2,%3}, {%4,%5,%6,%7}, {%8,%9}, {%0,%1,%2,%3};"
        : "+f"(c[0]), "+f"(c[1]), "+f"(c[2]), "+f"(c[3])
        : "r"(a[0]), "r"(a[1]), "r"(a[2]), "r"(a[3]), "r"(b0), "r"(b1));
}

__device__ __forceinline__ void cp_async16(uint32_t smem_addr, const void* gptr) {
    asm volatile("cp.async.cg.shared.global [%0], [%1], 16;"
                 :: "r"(smem_addr), "l"(gptr));
}

// ---------------------------------------------------------------------------
// Kernel A: tf32 tensor GEMM, cp.async double-buffered, A read directly
// from keys (fused transpose), fused ReLU/bias/Q-dot epilogue.
//   Y[m,c] = sum_d keysT[m,d] * W[c,d];  att[m] += relu(Y+bias[c])*Q[b, c&511]
// BM=128, BN=128, BK=32, 256 threads (2x4 warps), warp tile 64x32.
// smem: As[2][4096] (keys-native: bloc*512 + d*16 + k), Bs[2][128*36],
//       Qs[8*128], bias[128], part[128]
// ---------------------------------------------------------------------------
#define SSTR 36
#define A_TILE_F 4096
#define B_TILE_F (128 * SSTR)
#define GEMM_SMEM_BYTES ((2*A_TILE_F + 2*B_TILE_F + 8*128 + 128 + 128) * 4)

__global__ __launch_bounds__(256)
void gemm_att_tc(const float* __restrict__ keys, const float* __restrict__ W,
                 const float* __restrict__ bias, const float* __restrict__ query,
                 float* __restrict__ att) {
    extern __shared__ float smem[];
    float* As    = smem;                      // 2 * 4096
    float* Bs    = As + 2 * A_TILE_F;         // 2 * 4608
    float* Qs    = Bs + 2 * B_TILE_F;         // 1024
    float* biasS = Qs + 8 * 128;              // 128
    float* partS = biasS + 128;               // 128

    int tid  = threadIdx.x;
    int lane = tid & 31;
    int warp = tid >> 5;
    int warp_m = warp >> 2;        // 0..1
    int warp_n = warp & 3;         // 0..3
    int g   = lane >> 2;           // 0..7
    int tig = lane & 3;            // 0..3

    int c0 = blockIdx.x * 128;     // col tile (never crosses a head)
    int m0 = blockIdx.y * 128;     // row tile
    int q0 = c0 & (DQ - 1);
    int b0 = m0 >> 4;              // 8 batches per 128 rows

    uint32_t sA = (uint32_t)__cvta_generic_to_shared(As);
    uint32_t sB = (uint32_t)__cvta_generic_to_shared(Bs);

    // A-copy mapping: 1024 x 16B chunks per tile -> 4 per thread
    //   flat = bloc*128 + dl*8 + kkc  (bloc 0..7, dl 0..31 wait: per b: 32 dl * 4 kkc = 128)
    //   src  = keys[(b0+bloc)*8192 + (kt+dl)*16 + kkc*4]
    //   dst  = As + stage*4096 + bloc*512 + dl*16 + kkc*4
    int a_bloc = tid >> 5;                 // 0..7  (one warp per batch)
    int a_dl   = lane >> 2;                // 0..7  base d (x4 below)
    int a_kkc  = lane & 3;                 // 0..3
    // B-copy mapping: 1024 chunks: r = flat>>3, cc = flat&7; 4 per thread
    int b_r  = tid >> 1;                   // 0..127 (x? -> two rows... see loop)
    // use flat = i*256 + tid: r = flat>>3, cc = flat&7

    // Stage Q tile and bias; zero partials
    for (int i = tid; i < 8 * 128; i += 256)
        Qs[i] = query[(b0 + (i >> 7)) * DQ + q0 + (i & 127)];
    if (tid < 128) { biasS[tid] = bias[c0 + tid]; partS[tid] = 0.0f; }

    // async-copy one k-tile into stage s
    auto issue_tile = [&](int kt, int s) {
        uint32_t aBase = sA + (uint32_t)(s * A_TILE_F) * 4;
        uint32_t bBase = sB + (uint32_t)(s * B_TILE_F) * 4;
        #pragma unroll
        for (int i = 0; i < 4; i++) {
            int dl = a_dl + i * 8;     // 0..31
            const float* src = keys + (size_t)(b0 + a_bloc) * (DK * NK)
                             + (size_t)(kt + dl) * NK + a_kkc * 4;
            cp_async16(aBase + (uint32_t)(a_bloc * 512 + dl * 16 + a_kkc * 4) * 4, src);
        }
        #pragma unroll
        for (int i = 0; i < 4; i++) {
            int flat = i * 256 + tid;
            int r = flat >> 3, cc = flat & 7;
            const float* src = W + (size_t)(c0 + r) * DK + kt + cc * 4;
            cp_async16(bBase + (uint32_t)(r * SSTR + cc * 4) * 4, src);
        }
        asm volatile("cp.async.commit_group;");
    };

    float acc[4][4][4] = {};
    issue_tile(0, 0);

    for (int it = 0; it < 16; it++) {
        int buf = it & 1;
        if (it < 15) {
            issue_tile((it + 1) * 32, buf ^ 1);
            asm volatile("cp.async.wait_group 1;");
        } else {
            asm volatile("cp.async.wait_group 0;");
        }
        __syncthreads();

        const float* Ab = As + buf * A_TILE_F;   // [bloc*512 + d*16 + k]
        const float* Bb = Bs + buf * B_TILE_F;   // [n*36 + k]

        #pragma unroll
        for (int ks = 0; ks < 4; ks++) {
            int k = ks * 8 + tig;
            uint32_t a[4][4];
            #pragma unroll
            for (int mt = 0; mt < 4; mt++) {
                int bloc = warp_m * 4 + mt;          // (warp_m*64+mt*16)>>4
                const float* ab = &Ab[bloc * 512];
                a[mt][0] = __float_as_uint(ab[(k    ) * 16 + g    ]);
                a[mt][1] = __float_as_uint(ab[(k    ) * 16 + g + 8]);
                a[mt][2] = __float_as_uint(ab[(k + 4) * 16 + g    ]);
                a[mt][3] = __float_as_uint(ab[(k + 4) * 16 + g + 8]);
            }
            #pragma unroll
            for (int nt = 0; nt < 4; nt++) {
                int nbase = warp_n * 32 + nt * 8 + g;
                uint32_t b0r = __float_as_uint(Bb[nbase * SSTR + k    ]);
                uint32_t b1r = __float_as_uint(Bb[nbase * SSTR + k + 4]);
                #pragma unroll
                for (int mt = 0; mt < 4; mt++)
                    mma_tf32(acc[mt][nt], a[mt], b0r, b1r);
            }
        }
        __syncthreads();   // done reading buf before tile it+2 overwrites it
    }

    // Epilogue: bias + relu + Q-weight, reduce per row
    #pragma unroll
    for (int mt = 0; mt < 4; mt++) {
        int mlo = warp_m * 64 + mt * 16 + g;
        int mhi = mlo + 8;
        const float* q_lo = &Qs[(mlo >> 4) * 128];
        const float* q_hi = &Qs[(mhi >> 4) * 128];
        float p_lo = 0.0f, p_hi = 0.0f;
        #pragma unroll
        for (int nt = 0; nt < 4; nt++) {
            int cl = warp_n * 32 + nt * 8 + 2 * tig;
            float bi0 = biasS[cl], bi1 = biasS[cl + 1];
            p_lo = fmaf(fmaxf(acc[mt][nt][0] + bi0, 0.0f), q_lo[cl],     p_lo);
            p_lo = fmaf(fmaxf(acc[mt][nt][1] + bi1, 0.0f), q_lo[cl + 1], p_lo);
            p_hi = fmaf(fmaxf(acc[mt][nt][2] + bi0, 0.0f), q_hi[cl],     p_hi);
            p_hi = fmaf(fmaxf(acc[mt][nt][3] + bi1, 0.0f), q_hi[cl + 1], p_hi);
        }
        p_lo += __shfl_xor_sync(0xffffffffu, p_lo, 1);
        p_lo += __shfl_xor_sync(0xffffffffu, p_lo, 2);
        p_hi += __shfl_xor_sync(0xffffffffu, p_hi, 1);
        p_hi += __shfl_xor_sync(0xffffffffu, p_hi, 2);
        if (tig == 0) {
            atomicAdd(&partS[mlo], p_lo);
            atomicAdd(&partS[mhi], p_hi);
        }
    }
    __syncthreads();
    if (tid < 128) atomicAdd(&att[m0 + tid], partS[tid]);
}

// ---------------------------------------------------------------------------
// Kernel C: fused softmax (warp 0, redundant per block — free, DRAM-bound)
// + att-weighted V reduction. R2-proven body: 1 elem/thread, 4x float4.
// ---------------------------------------------------------------------------
__global__ __launch_bounds__(256)
void weighted_v_kernel(const float* __restrict__ V, const float* __restrict__ att,
                       float* __restrict__ out) {
    __shared__ float aw[NK];
    int b = blockIdx.y;
    if (threadIdx.x < 32) {
        int lane = threadIdx.x;
        const float scale = 1.0f / (8.0f * 22.62741699796952f);  // 1/(H*sqrt(512))
        float v = (lane < NK) ? att[b * NK + lane] * scale : -1e30f;
        float m = v;
        #pragma unroll
        for (int o = 8; o; o >>= 1) m = fmaxf(m, __shfl_xor_sync(0xffffffffu, m, o));
        float e = (lane < NK) ? __expf(v - m) : 0.0f;
        float s = e;
        #pragma unroll
        for (int o = 8; o; o >>= 1) s += __shfl_xor_sync(0xffffffffu, s, o);
        if (lane < NK) aw[lane] = e / s;
    }
    __syncthreads();

    int i = blockIdx.x * blockDim.x + threadIdx.x;
    if (i >= TNC) return;
    const float4* v4 = (const float4*)(V + ((size_t)b * TNC + i) * NK);
    float4 p0 = v4[0], p1 = v4[1], p2 = v4[2], p3 = v4[3];
    float s;
    s  = p0.x * aw[0]  + p0.y * aw[1]  + p0.z * aw[2]  + p0.w * aw[3];
    s += p1.x * aw[4]  + p1.y * aw[5]  + p1.z * aw[6]  + p1.w * aw[7];
    s += p2.x * aw[8]  + p2.y * aw[9]  + p2.z * aw[10] + p2.w * aw[11];
    s += p3.x * aw[12] + p3.y * aw[13] + p3.z * aw[14] + p3.w * aw[15];
    out[(size_t)b * TNC + i] = s;
}

// ---------------------------------------------------------------------------
extern "C" void kernel_launch(void* const* d_in, const int* in_sizes, int n_in,
                              void* d_out, int out_size) {
    const float *query = nullptr, *keys = nullptr, *V = nullptr,
                *W = nullptr, *bias = nullptr;
    for (int i = 0; i < n_in; i++) {
        switch (in_sizes[i]) {
            case Bn * DQ:            query = (const float*)d_in[i]; break;
            case Bn * DK * NK:       keys  = (const float*)d_in[i]; break;
            case Bn * TNC * NK:      V     = (const float*)d_in[i]; break;
            case Hn * DQ * DK:       W     = (const float*)d_in[i]; break;
            case Hn * DQ:            bias  = (const float*)d_in[i]; break;
            default: break;
        }
    }
    float* out = (float*)d_out;

    float* att; cudaGetSymbolAddress((void**)&att, g_att);

    cudaFuncSetAttribute(gemm_att_tc,
                         cudaFuncAttributeMaxDynamicSharedMemorySize,
                         GEMM_SMEM_BYTES);

    cudaMemsetAsync(att, 0, Mrows * sizeof(float));

    dim3 gridA(Ncols / 128, Mrows / 128);   // (32, 4)
    gemm_att_tc<<<gridA, 256, GEMM_SMEM_BYTES>>>(keys, W, bias, query, att);

    dim3 gridC(TNC / 256, Bn);              // (621, 32)
    weighted_v_kernel<<<gridC, 256>>>(V, att, out);
}

// round 5
// speedup vs baseline: 1.2545x; 1.0333x over previous
#include <cuda_runtime.h>
#include <cuda_bf16.h>
#include <math.h>
#include <stdint.h>

// Problem constants
#define Bn   32
#define DQ   512
#define DK   512
#define NK   16
#define Hn   8
#define Tt   12
#define Nn   207
#define Cc   64
#define TNC  (Tt*Nn*Cc)      // 158976
#define Mrows (Bn*NK)        // 512
#define Ncols (Hn*DQ)        // 4096
#define NXB  32              // GEMM col-tile blocks (4096/128)

__device__ float g_part[NXB * Mrows];  // per-colblock logits partials
__device__ float g_att[Mrows];         // softmax weights

// ---------------------------------------------------------------------------
__device__ __forceinline__ void mma_tf32(float* c, const uint32_t* a,
                                         uint32_t b0, uint32_t b1) {
    asm volatile(
        "mma.sync.aligned.m16n8k8.row.col.f32.tf32.tf32.f32 "
        "{%0,%1,%2,%3}, {%4,%5,%6,%7}, {%8,%9}, {%0,%1,%2,%3};"
        : "+f"(c[0]), "+f"(c[1]), "+f"(c[2]), "+f"(c[3])
        : "r"(a[0]), "r"(a[1]), "r"(a[2]), "r"(a[3]), "r"(b0), "r"(b1));
}

__device__ __forceinline__ void cp_async16(uint32_t smem_addr, const void* gptr) {
    asm volatile("cp.async.cg.shared.global [%0], [%1], 16;"
                 :: "r"(smem_addr), "l"(gptr));
}

// ---------------------------------------------------------------------------
// Kernel A: tf32 GEMM, cp.async double-buffered, A direct from keys (fused
// transpose, XOR-swizzled -> conflict-free fragment LDS), fused ReLU/bias/
// Q-dot epilogue. Writes per-colblock partial logits (no atomics).
// BM=128, BN=128, BK=32, 256 threads (2x4 warps), warp tile 64x32.
// ---------------------------------------------------------------------------
#define SSTR 36
#define A_TILE_F 4096
#define B_TILE_F (128 * SSTR)
#define GEMM_SMEM_BYTES ((2*A_TILE_F + 2*B_TILE_F + 8*128 + 128 + 128) * 4)

__global__ __launch_bounds__(256)
void gemm_att_tc(const float* __restrict__ keys, const float* __restrict__ W,
                 const float* __restrict__ bias, const float* __restrict__ query,
                 float* __restrict__ part) {
    extern __shared__ float smem[];
    float* As    = smem;                      // 2 * 4096  [bloc*512 + d*16 + nk] (swizzled)
    float* Bs    = As + 2 * A_TILE_F;         // 2 * 4608  [n*36 + d]
    float* Qs    = Bs + 2 * B_TILE_F;         // 1024
    float* biasS = Qs + 8 * 128;              // 128
    float* partS = biasS + 128;               // 128

    int tid  = threadIdx.x;
    int lane = tid & 31;
    int warp = tid >> 5;
    int warp_m = warp >> 2;        // 0..1
    int warp_n = warp & 3;         // 0..3
    int g   = lane >> 2;           // 0..7
    int tig = lane & 3;            // 0..3
    int swz = (tig & 2) << 2;      // fragment-read XOR (bit1 of d -> bit3)

    int c0 = blockIdx.x * 128;
    int m0 = blockIdx.y * 128;
    int q0 = c0 & (DQ - 1);
    int b0 = m0 >> 4;

    uint32_t sA = (uint32_t)__cvta_generic_to_shared(As);
    uint32_t sB = (uint32_t)__cvta_generic_to_shared(Bs);

    int a_bloc = tid >> 5;                 // 0..7
    int a_dl   = lane >> 2;                // 0..7
    int a_kkc  = lane & 3;                 // 0..3

    for (int i = tid; i < 8 * 128; i += 256)
        Qs[i] = query[(b0 + (i >> 7)) * DQ + q0 + (i & 127)];
    if (tid < 128) { biasS[tid] = bias[c0 + tid]; partS[tid] = 0.0f; }

    auto issue_tile = [&](int kt, int s) {
        uint32_t aBase = sA + (uint32_t)(s * A_TILE_F) * 4;
        uint32_t bBase = sB + (uint32_t)(s * B_TILE_F) * 4;
        #pragma unroll
        for (int i = 0; i < 4; i++) {
            int dl = a_dl + i * 8;     // 0..31
            const float* src = keys + (size_t)(b0 + a_bloc) * (DK * NK)
                             + (size_t)(kt + dl) * NK + a_kkc * 4;
            int woff = a_bloc * 512 + dl * 16 + ((a_kkc * 4) ^ ((dl & 2) << 2));
            cp_async16(aBase + (uint32_t)woff * 4, src);
        }
        #pragma unroll
        for (int i = 0; i < 4; i++) {
            int flat = i * 256 + tid;
            int r = flat >> 3, cc = flat & 7;
            const float* src = W + (size_t)(c0 + r) * DK + kt + cc * 4;
            cp_async16(bBase + (uint32_t)(r * SSTR + cc * 4) * 4, src);
        }
        asm volatile("cp.async.commit_group;");
    };

    float acc[4][4][4] = {};
    issue_tile(0, 0);

    for (int it = 0; it < 16; it++) {
        int buf = it & 1;
        if (it < 15) {
            issue_tile((it + 1) * 32, buf ^ 1);
            asm volatile("cp.async.wait_group 1;");
        } else {
            asm volatile("cp.async.wait_group 0;");
        }
        __syncthreads();

        const float* Ab = As + buf * A_TILE_F;
        const float* Bb = Bs + buf * B_TILE_F;

        #pragma unroll
        for (int ks = 0; ks < 4; ks++) {
            int k = ks * 8 + tig;              // d index 0..31 (bit1 == tig bit1)
            uint32_t a[4][4];
            #pragma unroll
            for (int mt = 0; mt < 4; mt++) {
                int bloc = warp_m * 4 + mt;
                const float* ab = &Ab[bloc * 512];
                a[mt][0] = __float_as_uint(ab[(k    ) * 16 + ( g      ^ swz)]);
                a[mt][1] = __float_as_uint(ab[(k    ) * 16 + ((g + 8) ^ swz)]);
                a[mt][2] = __float_as_uint(ab[(k + 4) * 16 + ( g      ^ swz)]);
                a[mt][3] = __float_as_uint(ab[(k + 4) * 16 + ((g + 8) ^ swz)]);
            }
            #pragma unroll
            for (int nt = 0; nt < 4; nt++) {
                int nbase = warp_n * 32 + nt * 8 + g;
                uint32_t b0r = __float_as_uint(Bb[nbase * SSTR + k    ]);
                uint32_t b1r = __float_as_uint(Bb[nbase * SSTR + k + 4]);
                #pragma unroll
                for (int mt = 0; mt < 4; mt++)
                    mma_tf32(acc[mt][nt], a[mt], b0r, b1r);
            }
        }
        __syncthreads();
    }

    // Epilogue: bias + relu + Q-weight, reduce per row
    #pragma unroll
    for (int mt = 0; mt < 4; mt++) {
        int mlo = warp_m * 64 + mt * 16 + g;
        int mhi = mlo + 8;
        const float* q_lo = &Qs[(mlo >> 4) * 128];
        const float* q_hi = &Qs[(mhi >> 4) * 128];
        float p_lo = 0.0f, p_hi = 0.0f;
        #pragma unroll
        for (int nt = 0; nt < 4; nt++) {
            int cl = warp_n * 32 + nt * 8 + 2 * tig;
            float bi0 = biasS[cl], bi1 = biasS[cl + 1];
            p_lo = fmaf(fmaxf(acc[mt][nt][0] + bi0, 0.0f), q_lo[cl],     p_lo);
            p_lo = fmaf(fmaxf(acc[mt][nt][1] + bi1, 0.0f), q_lo[cl + 1], p_lo);
            p_hi = fmaf(fmaxf(acc[mt][nt][2] + bi0, 0.0f), q_hi[cl],     p_hi);
            p_hi = fmaf(fmaxf(acc[mt][nt][3] + bi1, 0.0f), q_hi[cl + 1], p_hi);
        }
        p_lo += __shfl_xor_sync(0xffffffffu, p_lo, 1);
        p_lo += __shfl_xor_sync(0xffffffffu, p_lo, 2);
        p_hi += __shfl_xor_sync(0xffffffffu, p_hi, 1);
        p_hi += __shfl_xor_sync(0xffffffffu, p_hi, 2);
        if (tig == 0) {
            atomicAdd(&partS[mlo], p_lo);
            atomicAdd(&partS[mhi], p_hi);
        }
    }
    __syncthreads();
    if (tid < 128) part[blockIdx.x * Mrows + m0 + tid] = partS[tid];
}

// ---------------------------------------------------------------------------
// Kernel B: reduce per-colblock partials + softmax. One block per batch b.
// 512 threads: tid = xblk*16 + k.
// ---------------------------------------------------------------------------
__global__ __launch_bounds__(512)
void softmax_kernel(const float* __restrict__ part, float* __restrict__ att) {
    __shared__ float s[512];
    int b = blockIdx.x;
    int tid = threadIdx.x;
    int xblk = tid >> 4, k = tid & 15;
    s[tid] = part[xblk * Mrows + b * NK + k];
    __syncthreads();
    #pragma unroll
    for (int off = 256; off >= 16; off >>= 1) {
        if (tid < off) s[tid] += s[tid + off];
        __syncthreads();
    }
    if (tid < 32) {
        const float scale = 1.0f / (8.0f * 22.62741699796952f);  // 1/(H*sqrt(512))
        float v = (tid < NK) ? s[tid] * scale : -1e30f;
        float m = v;
        #pragma unroll
        for (int o = 8; o; o >>= 1) m = fmaxf(m, __shfl_xor_sync(0xffffffffu, m, o));
        float e = (tid < NK) ? __expf(v - m) : 0.0f;
        float z = e;
        #pragma unroll
        for (int o = 8; o; o >>= 1) z += __shfl_xor_sync(0xffffffffu, z, o);
        if (tid < NK) att[b * NK + tid] = e / z;
    }
}

// ---------------------------------------------------------------------------
// Kernel C: att-weighted V reduction (pure streaming, R1-proven body).
// launch_bounds(256,8) caps regs at 32 -> 8 CTAs/SM for latency hiding.
// ---------------------------------------------------------------------------
__global__ __launch_bounds__(256, 8)
void weighted_v_kernel(const float* __restrict__ V, const float* __restrict__ att,
                       float* __restrict__ out) {
    __shared__ float aw[NK];
    int b = blockIdx.y;
    if (threadIdx.x < NK) aw[threadIdx.x] = att[b * NK + threadIdx.x];
    __syncthreads();
    int i = blockIdx.x * blockDim.x + threadIdx.x;
    if (i >= TNC) return;
    const float4* v4 = (const float4*)(V + ((size_t)b * TNC + i) * NK);
    float4 p0 = v4[0], p1 = v4[1], p2 = v4[2], p3 = v4[3];
    float s;
    s  = p0.x * aw[0]  + p0.y * aw[1]  + p0.z * aw[2]  + p0.w * aw[3];
    s += p1.x * aw[4]  + p1.y * aw[5]  + p1.z * aw[6]  + p1.w * aw[7];
    s += p2.x * aw[8]  + p2.y * aw[9]  + p2.z * aw[10] + p2.w * aw[11];
    s += p3.x * aw[12] + p3.y * aw[13] + p3.z * aw[14] + p3.w * aw[15];
    out[(size_t)b * TNC + i] = s;
}

// ---------------------------------------------------------------------------
extern "C" void kernel_launch(void* const* d_in, const int* in_sizes, int n_in,
                              void* d_out, int out_size) {
    const float *query = nullptr, *keys = nullptr, *V = nullptr,
                *W = nullptr, *bias = nullptr;
    for (int i = 0; i < n_in; i++) {
        switch (in_sizes[i]) {
            case Bn * DQ:            query = (const float*)d_in[i]; break;
            case Bn * DK * NK:       keys  = (const float*)d_in[i]; break;
            case Bn * TNC * NK:      V     = (const float*)d_in[i]; break;
            case Hn * DQ * DK:       W     = (const float*)d_in[i]; break;
            case Hn * DQ:            bias  = (const float*)d_in[i]; break;
            default: break;
        }
    }
    float* out = (float*)d_out;

    float* part; cudaGetSymbolAddress((void**)&part, g_part);
    float* att;  cudaGetSymbolAddress((void**)&att,  g_att);

    cudaFuncSetAttribute(gemm_att_tc,
                         cudaFuncAttributeMaxDynamicSharedMemorySize,
                         GEMM_SMEM_BYTES);

    dim3 gridA(NXB, Mrows / 128);           // (32, 4)
    gemm_att_tc<<<gridA, 256, GEMM_SMEM_BYTES>>>(keys, W, bias, query, part);

    softmax_kernel<<<Bn, 512>>>(part, att);

    dim3 gridC(TNC / 256, Bn);              // (621, 32)
    weighted_v_kernel<<<gridC, 256>>>(V, att, out);
}